// round 3
// baseline (speedup 1.0000x reference)
#include <cuda_runtime.h>
#include <math.h>

#define Nn 10000
#define Ee 320000
#define K1P 672
#define K2P 1376

// ---------------- static scratch ----------------
__device__ int   d_is64;
__device__ int   d_src[Ee], d_dst[Ee], d_et[Ee], d_nt[Nn];
__device__ int   d_deg[Nn], d_off[Nn + 1], d_cur[Nn];
__device__ int   d_eid[Ee], d_srcS[Ee], d_etS[Ee];
__device__ float d_se1[Ee * 4], d_se2[Ee * 4];
__device__ float d_ssrc[Nn * 4], d_sdst[Nn * 4];
__device__ float d_u1[Nn * 64], d_u2[Nn * 256], d_h1[Nn * 256];
__device__ float d_v1[Nn * K1P], d_v2[(size_t)Nn * K2P];
__device__ float d_wsrc1[256], d_wdst1[256], d_wae1[256], d_etd1[22 * 4];
__device__ float d_wsrc2[1024], d_wdst2[1024], d_wae2[256], d_etd2[22 * 4];
__device__ float d_W1cat[K1P * 256], d_W2cat[K2P * 256];

__device__ __forceinline__ float lrelu(float v) { return v > 0.f ? v : 0.2f * v; }
__device__ __forceinline__ float comp4(float4 v, int h) {
    return h == 0 ? v.x : (h == 1 ? v.y : (h == 2 ? v.z : v.w));
}
__device__ __forceinline__ int ldidx(const void* p, long long i, int is64) {
    return is64 ? (int)((const long long*)p)[i] : ((const int*)p)[i];
}

// ---------------- dtype detect ----------------
__global__ void k_detect(const unsigned int* w) {
    __shared__ int f;
    if (threadIdx.x == 0) f = 1;
    __syncthreads();
    int bad = 0;
    for (int i = 1 + 2 * (int)threadIdx.x; i < Nn; i += 1024) if (w[i] != 0u) bad = 1;
    if (bad) atomicAnd(&f, 0);
    __syncthreads();
    if (threadIdx.x == 0) d_is64 = f;
}

__global__ void k_convert(const void* ei, const void* ntp, const void* etp) {
    int e = blockIdx.x * blockDim.x + threadIdx.x;
    int is64 = d_is64;
    if (e < Ee) {
        d_src[e] = ldidx(ei, e, is64);
        d_dst[e] = ldidx(ei, (long long)Ee + e, is64);
        d_et[e]  = ldidx(etp, e, is64);
    }
    if (e < Nn) { d_nt[e] = ldidx(ntp, e, is64); d_deg[e] = 0; }
}

__global__ void k_hist() {
    int e = blockIdx.x * blockDim.x + threadIdx.x;
    if (e < Ee) atomicAdd(&d_deg[d_dst[e]], 1);
}

__global__ void k_scan() {  // 1 block, 1024 threads
    __shared__ int s[1024];
    int t = threadIdx.x, base = t * 10, loc[10], sum = 0;
#pragma unroll
    for (int ii = 0; ii < 10; ii++) {
        int i = base + ii;
        int d = (i < Nn) ? d_deg[i] : 0;
        loc[ii] = d; sum += d;
    }
    s[t] = sum;
    __syncthreads();
    for (int o = 1; o < 1024; o <<= 1) {
        int v = (t >= o) ? s[t - o] : 0;
        __syncthreads();
        s[t] += v;
        __syncthreads();
    }
    int run = s[t] - sum;
#pragma unroll
    for (int ii = 0; ii < 10; ii++) {
        int i = base + ii;
        if (i < Nn) { d_off[i] = run; d_cur[i] = run; run += loc[ii]; }
        else if (i == Nn) d_off[Nn] = run;
    }
}

__global__ void k_scatter() {
    int e = blockIdx.x * blockDim.x + threadIdx.x;
    if (e < Ee) {
        int p = atomicAdd(&d_cur[d_dst[e]], 1);
        d_eid[p] = e; d_srcS[p] = d_src[e]; d_etS[p] = d_et[e];
    }
}

// ---------------- weight precompute: score vectors ----------------
__global__ void k_prew(const float* W1, const float* as1, const float* ad1,
                       const float* We1, const float* ag1, const float* etb1,
                       const float* W2, const float* as2, const float* ad2,
                       const float* We2, const float* ag2, const float* etb2) {
    int j = blockIdx.x * blockDim.x + threadIdx.x;
    if (j < 256) {
        int h = j >> 6, k = j & 63; float s = 0.f;
        for (int c = 0; c < 64; c++) s += W1[k * 256 + h * 64 + c] * as1[h * 64 + c];
        d_wsrc1[j] = s;
    } else if (j < 512) {
        int jj = j - 256, h = jj >> 6, k = jj & 63; float s = 0.f;
        for (int c = 0; c < 64; c++) s += W1[k * 256 + h * 64 + c] * ad1[h * 64 + c];
        d_wdst1[jj] = s;
    } else if (j < 768) {
        int jj = j - 512, h = jj >> 6, k = jj & 63; float s = 0.f;
        for (int c = 0; c < 64; c++) s += We1[k * 256 + h * 64 + c] * ag1[h * 64 + c];
        d_wae1[jj] = s;
    } else if (j < 856) {
        int jj = j - 768, t = jj >> 2, h = jj & 3; float s = 0.f;
        for (int c = 0; c < 64; c++) s += etb1[t * 256 + h * 64 + c] * ag1[h * 64 + c];
        d_etd1[jj] = s;
    } else if (j < 1880) {
        int jj = j - 856, h = jj >> 8, k = jj & 255; float s = 0.f;
        for (int c = 0; c < 256; c++) s += W2[k * 1024 + h * 256 + c] * as2[h * 256 + c];
        d_wsrc2[jj] = s;
    } else if (j < 2904) {
        int jj = j - 1880, h = jj >> 8, k = jj & 255; float s = 0.f;
        for (int c = 0; c < 256; c++) s += W2[k * 1024 + h * 256 + c] * ad2[h * 256 + c];
        d_wdst2[jj] = s;
    } else if (j < 3160) {
        int jj = j - 2904, h = jj >> 6, k = jj & 63; float s = 0.f;
        for (int c = 0; c < 256; c++) s += We2[k * 1024 + h * 256 + c] * ag2[h * 256 + c];
        d_wae2[jj] = s;
    } else if (j < 3248) {
        int jj = j - 3160, t = jj >> 2, h = jj & 3; float s = 0.f;
        for (int c = 0; c < 256; c++) s += etb2[t * 1024 + h * 256 + c] * ag2[h * 256 + c];
        d_etd2[jj] = s;
    }
}

// ---------------- concatenated finalize weights ----------------
__global__ void k_packw1(const float* W1, const float* We1, const float* etb1,
                         const float* res1) {
    int r = blockIdx.x, col = threadIdx.x;
    float v = 0.f;
    int hc = col >> 6;
    if (r < 256) { if ((r >> 6) == hc) v = W1[(r & 63) * 256 + col]; }
    else if (r < 512) { int rr = r - 256; if ((rr >> 6) == hc) v = We1[(rr & 63) * 256 + col]; }
    else if (r < 600) { int rr = r - 512, h = rr / 22, t = rr % 22; if (h == hc) v = etb1[t * 256 + col]; }
    else if (r < 664) v = res1[(r - 600) * 256 + col];
    d_W1cat[r * 256 + col] = v;
}

__global__ void k_packw2(const float* W2, const float* We2, const float* etb2) {
    int r = blockIdx.x, col = threadIdx.x;
    float v = 0.f;
    if (r < 1024) { int h = r >> 8, k = r & 255; v = W2[k * 1024 + h * 256 + col] * 0.25f; }
    else if (r < 1280) { int rr = r - 1024, h = rr >> 6, k = rr & 63; v = We2[k * 1024 + h * 256 + col] * 0.25f; }
    else if (r < 1368) { int rr = r - 1280, h = rr / 22, t = rr % 22; v = etb2[t * 1024 + h * 256 + col] * 0.25f; }
    d_W2cat[r * 256 + col] = v;
}

// ---------------- per-node u + node attention scores ----------------
__global__ void k_nscore(int layer, const float* x_l1, const float* ntemb) {
    int gw = (blockIdx.x * blockDim.x + threadIdx.x) >> 5;
    int lane = threadIdx.x & 31;
    if (gw >= Nn) return;
    const int K = (layer == 1) ? 64 : 256;
    const float* xin = (layer == 1) ? x_l1 : d_h1;
    const float* ws = (layer == 1) ? d_wsrc1 : d_wsrc2;
    const float* wd = (layer == 1) ? d_wdst1 : d_wdst2;
    float* u = (layer == 1) ? d_u1 : d_u2;
    int nt = d_nt[gw];
    float ps[4] = {0, 0, 0, 0}, pd[4] = {0, 0, 0, 0};
    for (int k = lane; k < K; k += 32) {
        float v = xin[gw * K + k] + ntemb[nt * K + k];
        u[gw * K + k] = v;
#pragma unroll
        for (int h = 0; h < 4; h++) { ps[h] += v * ws[h * K + k]; pd[h] += v * wd[h * K + k]; }
    }
#pragma unroll
    for (int h = 0; h < 4; h++)
        for (int o = 16; o > 0; o >>= 1) {
            ps[h] += __shfl_xor_sync(0xffffffffu, ps[h], o);
            pd[h] += __shfl_xor_sync(0xffffffffu, pd[h], o);
        }
    if (lane == 0)
#pragma unroll
        for (int h = 0; h < 4; h++) { d_ssrc[gw * 4 + h] = ps[h]; d_sdst[gw * 4 + h] = pd[h]; }
}

// ---------------- per-edge score contributions for both layers ----------------
__global__ void k_edgescore(const float* __restrict__ ea) {
    int i = (blockIdx.x * blockDim.x + threadIdx.x) >> 5;
    int lane = threadIdx.x & 31;
    if (i >= Ee) return;
    int e = d_eid[i];
    float a0 = ea[(size_t)e * 64 + lane];
    float a1 = ea[(size_t)e * 64 + 32 + lane];
    float dd1[4], dd2[4];
#pragma unroll
    for (int h = 0; h < 4; h++) {
        dd1[h] = a0 * d_wae1[h * 64 + lane] + a1 * d_wae1[h * 64 + 32 + lane];
        dd2[h] = a0 * d_wae2[h * 64 + lane] + a1 * d_wae2[h * 64 + 32 + lane];
        for (int o = 16; o > 0; o >>= 1) {
            dd1[h] += __shfl_xor_sync(0xffffffffu, dd1[h], o);
            dd2[h] += __shfl_xor_sync(0xffffffffu, dd2[h], o);
        }
    }
    if (lane == 0) {
        int et = d_etS[i];
#pragma unroll
        for (int h = 0; h < 4; h++) {
            d_se1[i * 4 + h] = dd1[h] + d_etd1[et * 4 + h];
            d_se2[i * 4 + h] = dd2[h] + d_etd2[et * 4 + h];
        }
    }
}

// softmax (max + sumexp) helper executed per block over [beg,end)
__device__ __forceinline__ void softmax_stats(const float4* se4, float4 sd,
                                              int beg, int end, int tid,
                                              float4* red, float4& m, float4& rdn) {
    const float4* ssrc4 = (const float4*)d_ssrc;
    float4 mx = make_float4(-1e30f, -1e30f, -1e30f, -1e30f);
    for (int i = beg + tid; i < end; i += 256) {
        float4 ss = ssrc4[d_srcS[i]]; float4 se = se4[i];
        mx.x = fmaxf(mx.x, lrelu(ss.x + sd.x + se.x));
        mx.y = fmaxf(mx.y, lrelu(ss.y + sd.y + se.y));
        mx.z = fmaxf(mx.z, lrelu(ss.z + sd.z + se.z));
        mx.w = fmaxf(mx.w, lrelu(ss.w + sd.w + se.w));
    }
    red[tid] = mx; __syncthreads();
    for (int o = 128; o > 0; o >>= 1) {
        if (tid < o) {
            float4 a = red[tid], b = red[tid + o];
            a.x = fmaxf(a.x, b.x); a.y = fmaxf(a.y, b.y);
            a.z = fmaxf(a.z, b.z); a.w = fmaxf(a.w, b.w);
            red[tid] = a;
        }
        __syncthreads();
    }
    m = red[0]; __syncthreads();
    float4 sm = make_float4(0, 0, 0, 0);
    for (int i = beg + tid; i < end; i += 256) {
        float4 ss = ssrc4[d_srcS[i]]; float4 se = se4[i];
        sm.x += __expf(lrelu(ss.x + sd.x + se.x) - m.x);
        sm.y += __expf(lrelu(ss.y + sd.y + se.y) - m.y);
        sm.z += __expf(lrelu(ss.z + sd.z + se.z) - m.z);
        sm.w += __expf(lrelu(ss.w + sd.w + se.w) - m.w);
    }
    red[tid] = sm; __syncthreads();
    for (int o = 128; o > 0; o >>= 1) {
        if (tid < o) {
            float4 a = red[tid], b = red[tid + o];
            a.x += b.x; a.y += b.y; a.z += b.z; a.w += b.w;
            red[tid] = a;
        }
        __syncthreads();
    }
    float4 den = red[0]; __syncthreads();
    rdn.x = 1.f / (den.x + 1e-16f); rdn.y = 1.f / (den.y + 1e-16f);
    rdn.z = 1.f / (den.z + 1e-16f); rdn.w = 1.f / (den.w + 1e-16f);
}

// ---------------- layer 1 attention + factored scatter ----------------
__global__ void k_attn1(const float* __restrict__ ea, const float* __restrict__ x) {
    int n = blockIdx.x, tid = threadIdx.x;
    __shared__ float4 red[256];
    __shared__ float4 aSh[256];
    __shared__ int srcSh[256], eidSh[256], etSh[256];
    __shared__ float acct[88];
    if (tid < 88) acct[tid] = 0.f;
    __syncthreads();
    int beg = d_off[n], end = d_off[n + 1];
    int h = tid >> 6, c = tid & 63;
    float ax = 0.f, ae = 0.f;
    if (end > beg) {
        const float4* ssrc4 = (const float4*)d_ssrc;
        const float4* se4 = (const float4*)d_se1;
        float4 sd = ((const float4*)d_sdst)[n];
        float4 m, rdn;
        softmax_stats(se4, sd, beg, end, tid, red, m, rdn);
        for (int c0 = beg; c0 < end; c0 += 256) {
            int nc = min(256, end - c0);
            if (tid < nc) {
                int i = c0 + tid, s = d_srcS[i];
                srcSh[tid] = s; eidSh[tid] = d_eid[i]; etSh[tid] = d_etS[i];
                float4 ss = ssrc4[s]; float4 se = se4[i]; float4 al;
                al.x = __expf(lrelu(ss.x + sd.x + se.x) - m.x) * rdn.x;
                al.y = __expf(lrelu(ss.y + sd.y + se.y) - m.y) * rdn.y;
                al.z = __expf(lrelu(ss.z + sd.z + se.z) - m.z) * rdn.z;
                al.w = __expf(lrelu(ss.w + sd.w + se.w) - m.w) * rdn.w;
                aSh[tid] = al;
            }
            __syncthreads();
            for (int j = 0; j < nc; j++) {
                float a = comp4(aSh[j], h);
                int s = srcSh[j], e = eidSh[j];
                ax += a * __ldg(&d_u1[s * 64 + c]);
                ae += a * __ldg(&ea[(size_t)e * 64 + c]);
                if (c == 0) acct[h * 22 + etSh[j]] += a;
            }
            __syncthreads();
        }
    }
    __syncthreads();
    float* v = &d_v1[(size_t)n * K1P];
    v[tid] = ax;
    v[256 + tid] = ae;
    if (tid < 88) v[512 + tid] = acct[tid];
    else if (tid < 152) v[600 + (tid - 88)] = x[n * 64 + (tid - 88)];
    else if (tid < 160) v[664 + (tid - 152)] = 0.f;
}

// ---------------- layer 2 attention + factored scatter ----------------
__global__ void k_attn2(const float* __restrict__ ea) {
    int n = blockIdx.x, tid = threadIdx.x;
    __shared__ float4 red[256];
    __shared__ float4 aSh[256];
    __shared__ int srcSh[256], eidSh[256], etSh[256];
    __shared__ float acct[88];
    if (tid < 88) acct[tid] = 0.f;
    __syncthreads();
    int beg = d_off[n], end = d_off[n + 1];
    int h = tid >> 6, c = tid & 63;
    float ax0 = 0.f, ax1 = 0.f, ax2 = 0.f, ax3 = 0.f, ae = 0.f;
    if (end > beg) {
        const float4* ssrc4 = (const float4*)d_ssrc;
        const float4* se4 = (const float4*)d_se2;
        float4 sd = ((const float4*)d_sdst)[n];
        float4 m, rdn;
        softmax_stats(se4, sd, beg, end, tid, red, m, rdn);
        for (int c0 = beg; c0 < end; c0 += 256) {
            int nc = min(256, end - c0);
            if (tid < nc) {
                int i = c0 + tid, s = d_srcS[i];
                srcSh[tid] = s; eidSh[tid] = d_eid[i]; etSh[tid] = d_etS[i];
                float4 ss = ssrc4[s]; float4 se = se4[i]; float4 al;
                al.x = __expf(lrelu(ss.x + sd.x + se.x) - m.x) * rdn.x;
                al.y = __expf(lrelu(ss.y + sd.y + se.y) - m.y) * rdn.y;
                al.z = __expf(lrelu(ss.z + sd.z + se.z) - m.z) * rdn.z;
                al.w = __expf(lrelu(ss.w + sd.w + se.w) - m.w) * rdn.w;
                aSh[tid] = al;
            }
            __syncthreads();
            for (int j = 0; j < nc; j++) {
                float4 al = aSh[j];
                int s = srcSh[j], e = eidSh[j];
                float u = __ldg(&d_u2[s * 256 + tid]);
                ax0 += al.x * u; ax1 += al.y * u; ax2 += al.z * u; ax3 += al.w * u;
                float a = comp4(al, h);
                ae += a * __ldg(&ea[(size_t)e * 64 + c]);
                if (c == 0) acct[h * 22 + etSh[j]] += a;
            }
            __syncthreads();
        }
    }
    __syncthreads();
    float* v = &d_v2[(size_t)n * K2P];
    v[tid] = ax0; v[256 + tid] = ax1; v[512 + tid] = ax2; v[768 + tid] = ax3;
    v[1024 + tid] = ae;
    if (tid < 88) v[1280 + tid] = acct[tid];
    else if (tid < 96) v[1280 + tid] = 0.f;
}

// ---------------- tiled SGEMM: C[Nn,256] = A[Nn,KPAD] @ B[KPAD,256] + epilogue --
template <int KPAD>
__global__ void k_gemm(const float* __restrict__ A, const float* __restrict__ B,
                       const float* __restrict__ bias, const float* __restrict__ add,
                       float* __restrict__ C, int do_relu) {
    __shared__ float As[16][64];
    __shared__ float Bs[16][64];
    int bm = blockIdx.x * 64, bn = blockIdx.y * 64;
    int tid = threadIdx.x;
    int tx = tid & 15, ty = tid >> 4;
    float acc[4][4] = {};
    int ar = tid >> 2, ak = (tid & 3) * 4;
    int kr = tid >> 4, bc = (tid & 15) * 4;
    for (int k0 = 0; k0 < KPAD; k0 += 16) {
        float4 av = make_float4(0, 0, 0, 0);
        int row = bm + ar;
        if (row < Nn) av = *(const float4*)&A[(size_t)row * KPAD + k0 + ak];
        As[ak + 0][ar] = av.x; As[ak + 1][ar] = av.y;
        As[ak + 2][ar] = av.z; As[ak + 3][ar] = av.w;
        float4 bv = *(const float4*)&B[(size_t)(k0 + kr) * 256 + bn + bc];
        Bs[kr][bc] = bv.x; Bs[kr][bc + 1] = bv.y; Bs[kr][bc + 2] = bv.z; Bs[kr][bc + 3] = bv.w;
        __syncthreads();
#pragma unroll
        for (int kk = 0; kk < 16; kk++) {
            float a0 = As[kk][ty * 4], a1 = As[kk][ty * 4 + 1];
            float a2 = As[kk][ty * 4 + 2], a3 = As[kk][ty * 4 + 3];
            float b0 = Bs[kk][tx * 4], b1 = Bs[kk][tx * 4 + 1];
            float b2 = Bs[kk][tx * 4 + 2], b3 = Bs[kk][tx * 4 + 3];
            acc[0][0] += a0 * b0; acc[0][1] += a0 * b1; acc[0][2] += a0 * b2; acc[0][3] += a0 * b3;
            acc[1][0] += a1 * b0; acc[1][1] += a1 * b1; acc[1][2] += a1 * b2; acc[1][3] += a1 * b3;
            acc[2][0] += a2 * b0; acc[2][1] += a2 * b1; acc[2][2] += a2 * b2; acc[2][3] += a2 * b3;
            acc[3][0] += a3 * b0; acc[3][1] += a3 * b1; acc[3][2] += a3 * b2; acc[3][3] += a3 * b3;
        }
        __syncthreads();
    }
#pragma unroll
    for (int i = 0; i < 4; i++) {
        int row = bm + ty * 4 + i;
        if (row >= Nn) continue;
#pragma unroll
        for (int j = 0; j < 4; j++) {
            int col = bn + tx * 4 + j;
            float v = acc[i][j] + bias[col];
            if (do_relu) v = fmaxf(v, 0.f);
            else v += add[row * 256 + col];
            C[row * 256 + col] = v;
        }
    }
}

// ---------------- launch ----------------
extern "C" void kernel_launch(void* const* d_in, const int* in_sizes, int n_in,
                              void* d_out, int out_size) {
    const float* x    = (const float*)d_in[0];
    const void*  ei   = d_in[1];
    const void*  ntp  = d_in[2];
    const float* ea   = (const float*)d_in[3];
    const void*  etp  = d_in[4];
    const float* W1   = (const float*)d_in[5];
    const float* b1   = (const float*)d_in[6];
    const float* We1  = (const float*)d_in[7];
    const float* nte1 = (const float*)d_in[8];
    const float* ete1 = (const float*)d_in[9];
    const float* as1  = (const float*)d_in[10];
    const float* ad1  = (const float*)d_in[11];
    const float* ag1  = (const float*)d_in[12];
    const float* res1 = (const float*)d_in[13];
    const float* W2   = (const float*)d_in[14];
    const float* b2   = (const float*)d_in[15];
    const float* We2  = (const float*)d_in[16];
    const float* nte2 = (const float*)d_in[17];
    const float* ete2 = (const float*)d_in[18];
    const float* as2  = (const float*)d_in[19];
    const float* ad2  = (const float*)d_in[20];
    const float* ag2  = (const float*)d_in[21];
    float* out = (float*)d_out;

    k_detect<<<1, 1024>>>((const unsigned int*)ntp);
    k_convert<<<(Ee + 255) / 256, 256>>>(ei, ntp, etp);
    k_hist<<<(Ee + 255) / 256, 256>>>();
    k_scan<<<1, 1024>>>();
    k_scatter<<<(Ee + 255) / 256, 256>>>();
    k_prew<<<13, 256>>>(W1, as1, ad1, We1, ag1, ete1, W2, as2, ad2, We2, ag2, ete2);
    k_packw1<<<K1P, 256>>>(W1, We1, ete1, res1);
    k_packw2<<<K2P, 256>>>(W2, We2, ete2);
    k_nscore<<<(Nn * 32 + 255) / 256, 256>>>(1, x, nte1);
    k_edgescore<<<(Ee * 32 + 255) / 256, 256>>>(ea);
    k_attn1<<<Nn, 256>>>(ea, x);
    {
        float* h1;
        cudaGetSymbolAddress((void**)&h1, d_h1);
        dim3 g((Nn + 63) / 64, 4);
        const float* v1;
        cudaGetSymbolAddress((void**)&v1, d_v1);
        const float* w1c;
        cudaGetSymbolAddress((void**)&w1c, d_W1cat);
        k_gemm<K1P><<<g, 256>>>(v1, w1c, b1, nullptr, h1, 1);
        k_nscore<<<(Nn * 32 + 255) / 256, 256>>>(2, x, nte2);
        k_attn2<<<Nn, 256>>>(ea);
        const float* v2;
        cudaGetSymbolAddress((void**)&v2, d_v2);
        const float* w2c;
        cudaGetSymbolAddress((void**)&w2c, d_W2cat);
        k_gemm<K2P><<<g, 256>>>(v2, w2c, b2, h1, out, 0);
    }
}

// round 4
// speedup vs baseline: 1.1158x; 1.1158x over previous
#include <cuda_runtime.h>
#include <math.h>

#define Nn 10000
#define Ee 320000
#define K1H 216          // per-head K for layer-1 GEMM (64 x + 64 e + 22 t + 64 res + 2 pad)
#define LDA1 (4 * K1H)   // 864
#define K2P 1376

// ---------------- static scratch ----------------
__device__ int   d_is64;
__device__ int   d_src[Ee], d_dst[Ee], d_et[Ee], d_nt[Nn];
__device__ int   d_deg[Nn], d_off[Nn + 1], d_cur[Nn];
__device__ int   d_eid[Ee], d_srcS[Ee], d_etS[Ee];
__device__ float d_se1[Ee * 4], d_se2[Ee * 4];
__device__ float d_ssrc[Nn * 4], d_sdst[Nn * 4];
__device__ float d_u1[Nn * 64], d_u2[Nn * 256], d_h1[Nn * 256];
__device__ float d_v1[(size_t)Nn * LDA1], d_v2[(size_t)Nn * K2P];
__device__ float d_wsrc1[256], d_wdst1[256], d_wae1[256], d_etd1[22 * 4];
__device__ float d_wsrc2[1024], d_wdst2[1024], d_wae2[256], d_etd2[22 * 4];
__device__ float d_W1h[4 * K1H * 64], d_W2cat[K2P * 256];

__device__ __forceinline__ float lrelu(float v) { return v > 0.f ? v : 0.2f * v; }
__device__ __forceinline__ float comp4(float4 v, int h) {
    return h == 0 ? v.x : (h == 1 ? v.y : (h == 2 ? v.z : v.w));
}
__device__ __forceinline__ int ldidx(const void* p, long long i, int is64) {
    return is64 ? (int)((const long long*)p)[i] : ((const int*)p)[i];
}

// f32x2 packed helpers (Blackwell)
__device__ __forceinline__ unsigned long long dup2(float x) {
    unsigned long long r;
    asm("mov.b64 %0, {%1, %1};" : "=l"(r) : "r"(__float_as_uint(x)));
    return r;
}
__device__ __forceinline__ void fma2(unsigned long long& d, unsigned long long a,
                                     unsigned long long b) {
    asm("fma.rn.f32x2 %0, %1, %2, %0;" : "+l"(d) : "l"(a), "l"(b));
}

// ---------------- dtype detect ----------------
__global__ void k_detect(const unsigned int* w) {
    __shared__ int f;
    if (threadIdx.x == 0) f = 1;
    __syncthreads();
    int bad = 0;
    for (int i = 1 + 2 * (int)threadIdx.x; i < Nn; i += 1024) if (w[i] != 0u) bad = 1;
    if (bad) atomicAnd(&f, 0);
    __syncthreads();
    if (threadIdx.x == 0) d_is64 = f;
}

__global__ void k_convert(const void* ei, const void* ntp, const void* etp) {
    int e = blockIdx.x * blockDim.x + threadIdx.x;
    int is64 = d_is64;
    if (e < Ee) {
        d_src[e] = ldidx(ei, e, is64);
        d_dst[e] = ldidx(ei, (long long)Ee + e, is64);
        d_et[e]  = ldidx(etp, e, is64);
    }
    if (e < Nn) { d_nt[e] = ldidx(ntp, e, is64); d_deg[e] = 0; }
}

__global__ void k_hist() {
    int e = blockIdx.x * blockDim.x + threadIdx.x;
    if (e < Ee) atomicAdd(&d_deg[d_dst[e]], 1);
}

__global__ void k_scan() {  // 1 block, 1024 threads, warp-shuffle scan
    __shared__ int wsum[32];
    int t = threadIdx.x, base = t * 10, loc[10], sum = 0;
#pragma unroll
    for (int ii = 0; ii < 10; ii++) {
        int i = base + ii;
        int d = (i < Nn) ? d_deg[i] : 0;
        loc[ii] = d; sum += d;
    }
    int lane = t & 31, w = t >> 5;
    int v = sum;
#pragma unroll
    for (int o = 1; o < 32; o <<= 1) {
        int u = __shfl_up_sync(0xffffffffu, v, o);
        if (lane >= o) v += u;
    }
    if (lane == 31) wsum[w] = v;
    __syncthreads();
    if (w == 0) {
        int s = wsum[lane];
#pragma unroll
        for (int o = 1; o < 32; o <<= 1) {
            int u = __shfl_up_sync(0xffffffffu, s, o);
            if (lane >= o) s += u;
        }
        wsum[lane] = s;
    }
    __syncthreads();
    int run = v - sum + (w ? wsum[w - 1] : 0);
#pragma unroll
    for (int ii = 0; ii < 10; ii++) {
        int i = base + ii;
        if (i < Nn) { d_off[i] = run; d_cur[i] = run; run += loc[ii]; }
        else if (i == Nn) d_off[Nn] = run;
    }
}

__global__ void k_scatter() {
    int e = blockIdx.x * blockDim.x + threadIdx.x;
    if (e < Ee) {
        int p = atomicAdd(&d_cur[d_dst[e]], 1);
        d_eid[p] = e; d_srcS[p] = d_src[e]; d_etS[p] = d_et[e];
    }
}

// ---------------- weight precompute: score vectors ----------------
__global__ void k_prew(const float* W1, const float* as1, const float* ad1,
                       const float* We1, const float* ag1, const float* etb1,
                       const float* W2, const float* as2, const float* ad2,
                       const float* We2, const float* ag2, const float* etb2) {
    int j = blockIdx.x * blockDim.x + threadIdx.x;
    if (j < 256) {
        int h = j >> 6, k = j & 63; float s = 0.f;
        for (int c = 0; c < 64; c++) s += W1[k * 256 + h * 64 + c] * as1[h * 64 + c];
        d_wsrc1[j] = s;
    } else if (j < 512) {
        int jj = j - 256, h = jj >> 6, k = jj & 63; float s = 0.f;
        for (int c = 0; c < 64; c++) s += W1[k * 256 + h * 64 + c] * ad1[h * 64 + c];
        d_wdst1[jj] = s;
    } else if (j < 768) {
        int jj = j - 512, h = jj >> 6, k = jj & 63; float s = 0.f;
        for (int c = 0; c < 64; c++) s += We1[k * 256 + h * 64 + c] * ag1[h * 64 + c];
        d_wae1[jj] = s;
    } else if (j < 856) {
        int jj = j - 768, t = jj >> 2, h = jj & 3; float s = 0.f;
        for (int c = 0; c < 64; c++) s += etb1[t * 256 + h * 64 + c] * ag1[h * 64 + c];
        d_etd1[jj] = s;
    } else if (j < 1880) {
        int jj = j - 856, h = jj >> 8, k = jj & 255; float s = 0.f;
        for (int c = 0; c < 256; c++) s += W2[k * 1024 + h * 256 + c] * as2[h * 256 + c];
        d_wsrc2[jj] = s;
    } else if (j < 2904) {
        int jj = j - 1880, h = jj >> 8, k = jj & 255; float s = 0.f;
        for (int c = 0; c < 256; c++) s += W2[k * 1024 + h * 256 + c] * ad2[h * 256 + c];
        d_wdst2[jj] = s;
    } else if (j < 3160) {
        int jj = j - 2904, h = jj >> 6, k = jj & 63; float s = 0.f;
        for (int c = 0; c < 256; c++) s += We2[k * 1024 + h * 256 + c] * ag2[h * 256 + c];
        d_wae2[jj] = s;
    } else if (j < 3248) {
        int jj = j - 3160, t = jj >> 2, h = jj & 3; float s = 0.f;
        for (int c = 0; c < 256; c++) s += etb2[t * 1024 + h * 256 + c] * ag2[h * 256 + c];
        d_etd2[jj] = s;
    }
}

// ---------------- per-head compact layer-1 weights: d_W1h[h][k][c] ----------------
__global__ void k_packw1(const float* W1, const float* We1, const float* etb1,
                         const float* res1) {
    int k = blockIdx.x, h = blockIdx.y, c = threadIdx.x;  // k<216, h<4, c<64
    float v = 0.f;
    if (k < 64) v = W1[k * 256 + h * 64 + c];
    else if (k < 128) v = We1[(k - 64) * 256 + h * 64 + c];
    else if (k < 150) v = etb1[(k - 128) * 256 + h * 64 + c];
    else if (k < 214) v = res1[(k - 150) * 256 + h * 64 + c];
    d_W1h[(h * K1H + k) * 64 + c] = v;
}

__global__ void k_packw2(const float* W2, const float* We2, const float* etb2) {
    int r = blockIdx.x, col = threadIdx.x;
    float v = 0.f;
    if (r < 1024) { int h = r >> 8, k = r & 255; v = W2[k * 1024 + h * 256 + col] * 0.25f; }
    else if (r < 1280) { int rr = r - 1024, h = rr >> 6, k = rr & 63; v = We2[k * 1024 + h * 256 + col] * 0.25f; }
    else if (r < 1368) { int rr = r - 1280, h = rr / 22, t = rr % 22; v = etb2[t * 1024 + h * 256 + col] * 0.25f; }
    d_W2cat[r * 256 + col] = v;
}

// ---------------- per-node u + node attention scores ----------------
__global__ void k_nscore(int layer, const float* x_l1, const float* ntemb) {
    int gw = (blockIdx.x * blockDim.x + threadIdx.x) >> 5;
    int lane = threadIdx.x & 31;
    if (gw >= Nn) return;
    const int K = (layer == 1) ? 64 : 256;
    const float* xin = (layer == 1) ? x_l1 : d_h1;
    const float* ws = (layer == 1) ? d_wsrc1 : d_wsrc2;
    const float* wd = (layer == 1) ? d_wdst1 : d_wdst2;
    float* u = (layer == 1) ? d_u1 : d_u2;
    int nt = d_nt[gw];
    float ps[4] = {0, 0, 0, 0}, pd[4] = {0, 0, 0, 0};
    for (int k = lane; k < K; k += 32) {
        float v = xin[gw * K + k] + ntemb[nt * K + k];
        u[gw * K + k] = v;
#pragma unroll
        for (int h = 0; h < 4; h++) { ps[h] += v * ws[h * K + k]; pd[h] += v * wd[h * K + k]; }
    }
#pragma unroll
    for (int h = 0; h < 4; h++)
        for (int o = 16; o > 0; o >>= 1) {
            ps[h] += __shfl_xor_sync(0xffffffffu, ps[h], o);
            pd[h] += __shfl_xor_sync(0xffffffffu, pd[h], o);
        }
    if (lane == 0)
#pragma unroll
        for (int h = 0; h < 4; h++) { d_ssrc[gw * 4 + h] = ps[h]; d_sdst[gw * 4 + h] = pd[h]; }
}

// ---------------- per-edge score contributions for both layers ----------------
__global__ void k_edgescore(const float* __restrict__ ea) {
    int i = (blockIdx.x * blockDim.x + threadIdx.x) >> 5;
    int lane = threadIdx.x & 31;
    if (i >= Ee) return;
    int e = d_eid[i];
    float a0 = ea[(size_t)e * 64 + lane];
    float a1 = ea[(size_t)e * 64 + 32 + lane];
    float dd1[4], dd2[4];
#pragma unroll
    for (int h = 0; h < 4; h++) {
        dd1[h] = a0 * d_wae1[h * 64 + lane] + a1 * d_wae1[h * 64 + 32 + lane];
        dd2[h] = a0 * d_wae2[h * 64 + lane] + a1 * d_wae2[h * 64 + 32 + lane];
        for (int o = 16; o > 0; o >>= 1) {
            dd1[h] += __shfl_xor_sync(0xffffffffu, dd1[h], o);
            dd2[h] += __shfl_xor_sync(0xffffffffu, dd2[h], o);
        }
    }
    if (lane == 0) {
        int et = d_etS[i];
#pragma unroll
        for (int h = 0; h < 4; h++) {
            d_se1[i * 4 + h] = dd1[h] + d_etd1[et * 4 + h];
            d_se2[i * 4 + h] = dd2[h] + d_etd2[et * 4 + h];
        }
    }
}

// softmax (max + sumexp) helper executed per block over [beg,end)
__device__ __forceinline__ void softmax_stats(const float4* se4, float4 sd,
                                              int beg, int end, int tid,
                                              float4* red, float4& m, float4& rdn) {
    const float4* ssrc4 = (const float4*)d_ssrc;
    float4 mx = make_float4(-1e30f, -1e30f, -1e30f, -1e30f);
    for (int i = beg + tid; i < end; i += 256) {
        float4 ss = ssrc4[d_srcS[i]]; float4 se = se4[i];
        mx.x = fmaxf(mx.x, lrelu(ss.x + sd.x + se.x));
        mx.y = fmaxf(mx.y, lrelu(ss.y + sd.y + se.y));
        mx.z = fmaxf(mx.z, lrelu(ss.z + sd.z + se.z));
        mx.w = fmaxf(mx.w, lrelu(ss.w + sd.w + se.w));
    }
    red[tid] = mx; __syncthreads();
    for (int o = 128; o > 0; o >>= 1) {
        if (tid < o) {
            float4 a = red[tid], b = red[tid + o];
            a.x = fmaxf(a.x, b.x); a.y = fmaxf(a.y, b.y);
            a.z = fmaxf(a.z, b.z); a.w = fmaxf(a.w, b.w);
            red[tid] = a;
        }
        __syncthreads();
    }
    m = red[0]; __syncthreads();
    float4 sm = make_float4(0, 0, 0, 0);
    for (int i = beg + tid; i < end; i += 256) {
        float4 ss = ssrc4[d_srcS[i]]; float4 se = se4[i];
        sm.x += __expf(lrelu(ss.x + sd.x + se.x) - m.x);
        sm.y += __expf(lrelu(ss.y + sd.y + se.y) - m.y);
        sm.z += __expf(lrelu(ss.z + sd.z + se.z) - m.z);
        sm.w += __expf(lrelu(ss.w + sd.w + se.w) - m.w);
    }
    red[tid] = sm; __syncthreads();
    for (int o = 128; o > 0; o >>= 1) {
        if (tid < o) {
            float4 a = red[tid], b = red[tid + o];
            a.x += b.x; a.y += b.y; a.z += b.z; a.w += b.w;
            red[tid] = a;
        }
        __syncthreads();
    }
    float4 den = red[0]; __syncthreads();
    rdn.x = 1.f / (den.x + 1e-16f); rdn.y = 1.f / (den.y + 1e-16f);
    rdn.z = 1.f / (den.z + 1e-16f); rdn.w = 1.f / (den.w + 1e-16f);
}

// ---------------- layer 1 attention + factored scatter (per-head v1 layout) -----
__global__ void k_attn1(const float* __restrict__ ea, const float* __restrict__ x) {
    int n = blockIdx.x, tid = threadIdx.x;
    __shared__ float4 red[256];
    __shared__ float4 aSh[256];
    __shared__ int srcSh[256], eidSh[256], etSh[256];
    __shared__ float acct[88];
    if (tid < 88) acct[tid] = 0.f;
    __syncthreads();
    int beg = d_off[n], end = d_off[n + 1];
    int h = tid >> 6, c = tid & 63;
    float ax = 0.f, ae = 0.f;
    if (end > beg) {
        const float4* ssrc4 = (const float4*)d_ssrc;
        const float4* se4 = (const float4*)d_se1;
        float4 sd = ((const float4*)d_sdst)[n];
        float4 m, rdn;
        softmax_stats(se4, sd, beg, end, tid, red, m, rdn);
        for (int c0 = beg; c0 < end; c0 += 256) {
            int nc = min(256, end - c0);
            if (tid < nc) {
                int i = c0 + tid, s = d_srcS[i];
                srcSh[tid] = s; eidSh[tid] = d_eid[i]; etSh[tid] = d_etS[i];
                float4 ss = ssrc4[s]; float4 se = se4[i]; float4 al;
                al.x = __expf(lrelu(ss.x + sd.x + se.x) - m.x) * rdn.x;
                al.y = __expf(lrelu(ss.y + sd.y + se.y) - m.y) * rdn.y;
                al.z = __expf(lrelu(ss.z + sd.z + se.z) - m.z) * rdn.z;
                al.w = __expf(lrelu(ss.w + sd.w + se.w) - m.w) * rdn.w;
                aSh[tid] = al;
            }
            __syncthreads();
            for (int j = 0; j < nc; j++) {
                float a = comp4(aSh[j], h);
                int s = srcSh[j], e = eidSh[j];
                ax += a * __ldg(&d_u1[s * 64 + c]);
                ae += a * __ldg(&ea[(size_t)e * 64 + c]);
                if (c == 0) acct[h * 22 + etSh[j]] += a;
            }
            __syncthreads();
        }
    }
    __syncthreads();
    float* v = &d_v1[(size_t)n * LDA1];
    v[h * K1H + c] = ax;
    v[h * K1H + 64 + c] = ae;
    v[h * K1H + 150 + c] = x[n * 64 + c];
    if (tid < 88) { int hh = tid / 22, t2 = tid % 22; v[hh * K1H + 128 + t2] = acct[tid]; }
    if (tid < 8) v[(tid >> 1) * K1H + 214 + (tid & 1)] = 0.f;
}

// ---------------- layer 2 attention + factored scatter ----------------
__global__ void k_attn2(const float* __restrict__ ea) {
    int n = blockIdx.x, tid = threadIdx.x;
    __shared__ float4 red[256];
    __shared__ float4 aSh[256];
    __shared__ int srcSh[256], eidSh[256], etSh[256];
    __shared__ float acct[88];
    if (tid < 88) acct[tid] = 0.f;
    __syncthreads();
    int beg = d_off[n], end = d_off[n + 1];
    int h = tid >> 6, c = tid & 63;
    float ax0 = 0.f, ax1 = 0.f, ax2 = 0.f, ax3 = 0.f, ae = 0.f;
    if (end > beg) {
        const float4* ssrc4 = (const float4*)d_ssrc;
        const float4* se4 = (const float4*)d_se2;
        float4 sd = ((const float4*)d_sdst)[n];
        float4 m, rdn;
        softmax_stats(se4, sd, beg, end, tid, red, m, rdn);
        for (int c0 = beg; c0 < end; c0 += 256) {
            int nc = min(256, end - c0);
            if (tid < nc) {
                int i = c0 + tid, s = d_srcS[i];
                srcSh[tid] = s; eidSh[tid] = d_eid[i]; etSh[tid] = d_etS[i];
                float4 ss = ssrc4[s]; float4 se = se4[i]; float4 al;
                al.x = __expf(lrelu(ss.x + sd.x + se.x) - m.x) * rdn.x;
                al.y = __expf(lrelu(ss.y + sd.y + se.y) - m.y) * rdn.y;
                al.z = __expf(lrelu(ss.z + sd.z + se.z) - m.z) * rdn.z;
                al.w = __expf(lrelu(ss.w + sd.w + se.w) - m.w) * rdn.w;
                aSh[tid] = al;
            }
            __syncthreads();
            for (int j = 0; j < nc; j++) {
                float4 al = aSh[j];
                int s = srcSh[j], e = eidSh[j];
                float u = __ldg(&d_u2[s * 256 + tid]);
                ax0 += al.x * u; ax1 += al.y * u; ax2 += al.z * u; ax3 += al.w * u;
                float a = comp4(al, h);
                ae += a * __ldg(&ea[(size_t)e * 64 + c]);
                if (c == 0) acct[h * 22 + etSh[j]] += a;
            }
            __syncthreads();
        }
    }
    __syncthreads();
    float* v = &d_v2[(size_t)n * K2P];
    v[tid] = ax0; v[256 + tid] = ax1; v[512 + tid] = ax2; v[768 + tid] = ax3;
    v[1024 + tid] = ae;
    if (tid < 88) v[1280 + tid] = acct[tid];
    else if (tid < 96) v[1280 + tid] = 0.f;
}

// ---------------- f32x2 packed SGEMM ----------------
// MODE 1: per-head layer-1 (K=216, lda=864, A col offset y*216, B=[4][216][64], relu+bias)
// MODE 2: dense layer-2 (K=1376, lda=1376, B=[1376][256] col tile y*64, bias+add)
template <int K, int MODE>
__global__ void k_gemmT(const float* __restrict__ A, const float* __restrict__ B,
                        const float* __restrict__ bias, const float* __restrict__ add,
                        float* __restrict__ C) {
    constexpr int LDA = (MODE == 1) ? LDA1 : K2P;
    __shared__ float As[8][132];
    __shared__ float Bs[8][64];
    int y = blockIdx.y;
    int bm = blockIdx.x * 128;
    int colbase = y * 64;
    const float* Ab = A + ((MODE == 1) ? y * K1H : 0);
    const float* Bb = (MODE == 1) ? (B + y * K1H * 64) : (B + colbase);
    const int ldb = (MODE == 1) ? 64 : 256;
    int tid = threadIdx.x;
    int tx = tid & 15, ty = tid >> 4;
    int lrow = tid >> 1, lk = (tid & 1) * 4;
    int brow = tid >> 4, bcol = (tid & 15) * 4;
    unsigned long long acc[4][4];
#pragma unroll
    for (int p = 0; p < 4; p++)
#pragma unroll
        for (int j = 0; j < 4; j++) acc[p][j] = 0ull;
    for (int k0 = 0; k0 < K; k0 += 8) {
        float4 av = make_float4(0, 0, 0, 0);
        int row = bm + lrow;
        if (row < Nn) av = *(const float4*)&Ab[(size_t)row * LDA + k0 + lk];
        As[lk + 0][lrow] = av.x; As[lk + 1][lrow] = av.y;
        As[lk + 2][lrow] = av.z; As[lk + 3][lrow] = av.w;
        if (tid < 128) {
            float4 bv = *(const float4*)&Bb[(size_t)(k0 + brow) * ldb + bcol];
            *(float4*)&Bs[brow][bcol] = bv;
        }
        __syncthreads();
#pragma unroll
        for (int kk = 0; kk < 8; kk++) {
            ulonglong2 a01 = *(const ulonglong2*)&As[kk][ty * 8];
            ulonglong2 a23 = *(const ulonglong2*)&As[kk][ty * 8 + 4];
            float4 bv = *(const float4*)&Bs[kk][tx * 4];
            unsigned long long ap[4] = {a01.x, a01.y, a23.x, a23.y};
            unsigned long long bd[4] = {dup2(bv.x), dup2(bv.y), dup2(bv.z), dup2(bv.w)};
#pragma unroll
            for (int p = 0; p < 4; p++)
#pragma unroll
                for (int j = 0; j < 4; j++) fma2(acc[p][j], ap[p], bd[j]);
        }
        __syncthreads();
    }
#pragma unroll
    for (int p = 0; p < 4; p++) {
        int r0 = bm + ty * 8 + 2 * p;
#pragma unroll
        for (int j = 0; j < 4; j++) {
            int col = colbase + tx * 4 + j;
            float lo = __uint_as_float((unsigned)(acc[p][j] & 0xffffffffull));
            float hi = __uint_as_float((unsigned)(acc[p][j] >> 32));
            float bsv = bias[col];
            if (r0 < Nn) {
                float v = lo + bsv;
                if (MODE == 1) v = fmaxf(v, 0.f);
                else v += add[r0 * 256 + col];
                C[r0 * 256 + col] = v;
            }
            if (r0 + 1 < Nn) {
                float v = hi + bsv;
                if (MODE == 1) v = fmaxf(v, 0.f);
                else v += add[(r0 + 1) * 256 + col];
                C[(r0 + 1) * 256 + col] = v;
            }
        }
    }
}

// ---------------- launch ----------------
extern "C" void kernel_launch(void* const* d_in, const int* in_sizes, int n_in,
                              void* d_out, int out_size) {
    const float* x    = (const float*)d_in[0];
    const void*  ei   = d_in[1];
    const void*  ntp  = d_in[2];
    const float* ea   = (const float*)d_in[3];
    const void*  etp  = d_in[4];
    const float* W1   = (const float*)d_in[5];
    const float* b1   = (const float*)d_in[6];
    const float* We1  = (const float*)d_in[7];
    const float* nte1 = (const float*)d_in[8];
    const float* ete1 = (const float*)d_in[9];
    const float* as1  = (const float*)d_in[10];
    const float* ad1  = (const float*)d_in[11];
    const float* ag1  = (const float*)d_in[12];
    const float* res1 = (const float*)d_in[13];
    const float* W2   = (const float*)d_in[14];
    const float* b2   = (const float*)d_in[15];
    const float* We2  = (const float*)d_in[16];
    const float* nte2 = (const float*)d_in[17];
    const float* ete2 = (const float*)d_in[18];
    const float* as2  = (const float*)d_in[19];
    const float* ad2  = (const float*)d_in[20];
    const float* ag2  = (const float*)d_in[21];
    float* out = (float*)d_out;

    k_detect<<<1, 1024>>>((const unsigned int*)ntp);
    k_convert<<<(Ee + 255) / 256, 256>>>(ei, ntp, etp);
    k_hist<<<(Ee + 255) / 256, 256>>>();
    k_scan<<<1, 1024>>>();
    k_scatter<<<(Ee + 255) / 256, 256>>>();
    k_prew<<<13, 256>>>(W1, as1, ad1, We1, ag1, ete1, W2, as2, ad2, We2, ag2, ete2);
    {
        dim3 gp(K1H, 4);
        k_packw1<<<gp, 64>>>(W1, We1, ete1, res1);
    }
    k_packw2<<<K2P, 256>>>(W2, We2, ete2);
    k_nscore<<<(Nn * 32 + 255) / 256, 256>>>(1, x, nte1);
    k_edgescore<<<(Ee * 32 + 255) / 256, 256>>>(ea);
    k_attn1<<<Nn, 256>>>(ea, x);
    {
        float* h1;   cudaGetSymbolAddress((void**)&h1, d_h1);
        float* v1;   cudaGetSymbolAddress((void**)&v1, d_v1);
        float* w1h;  cudaGetSymbolAddress((void**)&w1h, d_W1h);
        float* v2;   cudaGetSymbolAddress((void**)&v2, d_v2);
        float* w2c;  cudaGetSymbolAddress((void**)&w2c, d_W2cat);
        dim3 g((Nn + 127) / 128, 4);
        k_gemmT<K1H, 1><<<g, 256>>>(v1, w1h, b1, nullptr, h1);
        k_nscore<<<(Nn * 32 + 255) / 256, 256>>>(2, x, nte2);
        k_attn2<<<Nn, 256>>>(ea);
        k_gemmT<K2P, 2><<<g, 256>>>(v2, w2c, b2, h1, out);
    }
}